// round 11
// baseline (speedup 1.0000x reference)
#include <cuda_runtime.h>
#include <cstdint>

constexpr int BB = 32;       // batch (== warp width, lane = b)
constexpr int TT = 2048;     // time steps
constexpr int NSTEPS = TT + 6;
constexpr int GRID = 148;    // 4 * 37 exactly
constexpr int NTHR = 512;    // 16 warps -> 4 per SMSP (latency cover)

// ---------------- scratch (static device globals) ---------------------------
__device__ float g_xg[(size_t)BB * TT * 1536];   // L0 input projections [b*TT+t][1536]
__device__ float g_wT[256 * 1536];               // L0 w_ih transposed [K][3H]
__device__ float g_hr[8 * 32 * 1024];            // h rings [layer 0..3][par] f4[k>>2][b][k&3]
__device__ float g_xr[6 * 3072 * 32];            // xg rings [layer-1][par][row][b]
__device__ unsigned g_sub[4 * 64];               // tree barrier sub-counters (256B-strided)
__device__ unsigned g_root;
__device__ unsigned g_gen;

// ---------------- packed f32x2 helpers --------------------------------------
__device__ __forceinline__ void fma2(unsigned long long& a, unsigned long long x, unsigned long long y) {
    asm("fma.rn.f32x2 %0, %1, %2, %0;" : "+l"(a) : "l"(x), "l"(y));
}
__device__ __forceinline__ unsigned long long pk2(float x, float y) {
    unsigned long long r; asm("mov.b64 %0, {%1,%2};" : "=l"(r) : "f"(x), "f"(y)); return r;
}
__device__ __forceinline__ float2 up2(unsigned long long v) {
    float2 f; asm("mov.b64 {%0,%1}, %2;" : "=f"(f.x), "=f"(f.y) : "l"(v)); return f;
}
union HU { float4 f; ulonglong2 u; };

__device__ __forceinline__ void cpa16(void* dst, const void* src) {
    uint32_t d = (uint32_t)__cvta_generic_to_shared(dst);
    asm volatile("cp.async.cg.shared.global [%0], [%1], 16;" :: "r"(d), "l"(src));
}
__device__ __forceinline__ void st_rel(unsigned* p, unsigned v) {
    asm volatile("st.release.gpu.global.u32 [%0], %1;" :: "l"(p), "r"(v) : "memory");
}
__device__ __forceinline__ unsigned ld_acq(const unsigned* p) {
    unsigned v;
    asm volatile("ld.acquire.gpu.global.u32 %0, [%1];" : "=r"(v) : "l"(p) : "memory");
    return v;
}
__device__ __forceinline__ unsigned atom_add_ar(unsigned* p, unsigned v) {
    unsigned old;
    asm volatile("atom.acq_rel.gpu.global.add.u32 %0, [%1], %2;"
                 : "=r"(old) : "l"(p), "r"(v) : "memory");
    return old;
}

// ---------------- tree grid barrier -----------------------------------------
__device__ __forceinline__ void grid_barrier(int tid, int cta, unsigned tstep) {
    __syncthreads();
    if (tid == 0) {
        int sub = cta & 3;
        unsigned old = atom_add_ar(&g_sub[sub * 64], 1u);
        bool rootlast = false;
        if (old + 1u == 37u * tstep) {
            unsigned ro = atom_add_ar(&g_root, 1u);
            if (ro + 1u == 4u * tstep) { st_rel(&g_gen, tstep); rootlast = true; }
        }
        if (!rootlast)
            while ((int)(ld_acq(&g_gen) - tstep) < 0) { }
    }
    __syncthreads();
}

// ---------------- one-shot weight transpose: Wt[k][n] = W[n][k] -------------
__global__ void transpose_w(const float* __restrict__ W, float* __restrict__ Wt,
                            int K, int N3)
{
    __shared__ float tile[32][33];
    int kb = blockIdx.x * 32, nb = blockIdx.y * 32;
    for (int r = threadIdx.y; r < 32; r += 8)
        tile[r][threadIdx.x] = W[(size_t)(nb + r) * K + kb + threadIdx.x];
    __syncthreads();
    for (int r = threadIdx.y; r < 32; r += 8)
        Wt[(size_t)(kb + r) * N3 + nb + threadIdx.x] = tile[threadIdx.x][r];
}

// ---------------- bulk L0 input-projection GEMM (proven) --------------------
// Adds b_ih[n] + (n < 2H ? b_hh[n] : 0) — r/z parts of b_hh pre-folded.
__global__ __launch_bounds__(256, 2) void gemm_xg(
    const float* __restrict__ A, const float* __restrict__ Wt,
    const float* __restrict__ bih, const float* __restrict__ bhh,
    float* __restrict__ C, int K, int N3, int H, long sb)
{
    extern __shared__ __align__(16) float dsm[];
    float* As = dsm;                    // [3][16][128]
    float* Bs = dsm + 3 * 16 * 128;     // [3][16][128]

    int tid = threadIdx.x;
    int n0 = blockIdx.x * 128;
    int m0 = blockIdx.y * 128;
    int bidx = m0 / TT;
    int t0 = m0 % TT;
    const float* Ab = A + (size_t)bidx * sb + t0;
    int tx = tid & 15, ty = tid >> 4;

    unsigned long long acc[4][8];
#pragma unroll
    for (int p = 0; p < 4; ++p)
#pragma unroll
        for (int j = 0; j < 8; ++j) acc[p][j] = 0ull;

    auto issue = [&](int s, int k0) {
#pragma unroll
        for (int i = 0; i < 2; ++i) {
            int lin = tid + i * 256;
            int k = lin >> 5, q4 = (lin & 31) * 4;
            cpa16(&As[(s * 16 + k) * 128 + q4], Ab + q4 + (size_t)(k0 + k) * TT);
            cpa16(&Bs[(s * 16 + k) * 128 + q4], &Wt[(size_t)(k0 + k) * N3 + n0 + q4]);
        }
    };

    issue(0, 0);  asm volatile("cp.async.commit_group;" ::: "memory");
    issue(1, 16); asm volatile("cp.async.commit_group;" ::: "memory");

    int s = 0;
#pragma unroll 1
    for (int k0 = 0; k0 < K; k0 += 16) {
        asm volatile("cp.async.wait_group 1;" ::: "memory");
        __syncthreads();
        if (k0 + 32 < K) issue((s + 2) % 3, k0 + 32);
        asm volatile("cp.async.commit_group;" ::: "memory");

        const float* Ak = &As[s * 16 * 128];
        const float* Bk = &Bs[s * 16 * 128];
#pragma unroll
        for (int k = 0; k < 16; ++k) {
            const ulonglong2* ap = (const ulonglong2*)&Ak[k * 128 + ty * 8];
            ulonglong2 A0 = ap[0], A1 = ap[1];
            unsigned long long am[4] = {A0.x, A0.y, A1.x, A1.y};
            float4 b0 = *(const float4*)&Bk[k * 128 + tx * 8];
            float4 b1 = *(const float4*)&Bk[k * 128 + tx * 8 + 4];
            unsigned long long bd[8] = {pk2(b0.x, b0.x), pk2(b0.y, b0.y),
                                        pk2(b0.z, b0.z), pk2(b0.w, b0.w),
                                        pk2(b1.x, b1.x), pk2(b1.y, b1.y),
                                        pk2(b1.z, b1.z), pk2(b1.w, b1.w)};
#pragma unroll
            for (int p = 0; p < 4; ++p)
#pragma unroll
                for (int j = 0; j < 8; ++j) fma2(acc[p][j], am[p], bd[j]);
        }
        s = (s == 2) ? 0 : s + 1;
    }

    float bias[8];
#pragma unroll
    for (int j = 0; j < 8; ++j) {
        int n = n0 + tx * 8 + j;
        bias[j] = bih[n] + (n < 2 * H ? bhh[n] : 0.f);
    }
#pragma unroll
    for (int p = 0; p < 4; ++p) {
        float2 c[8];
#pragma unroll
        for (int j = 0; j < 8; ++j) c[j] = up2(acc[p][j]);
        size_t r0 = (size_t)(m0 + ty * 8 + 2 * p) * N3 + n0 + tx * 8;
        float4 lo0 = {c[0].x + bias[0], c[1].x + bias[1], c[2].x + bias[2], c[3].x + bias[3]};
        float4 hi0 = {c[4].x + bias[4], c[5].x + bias[5], c[6].x + bias[6], c[7].x + bias[7]};
        float4 lo1 = {c[0].y + bias[0], c[1].y + bias[1], c[2].y + bias[2], c[3].y + bias[3]};
        float4 hi1 = {c[4].y + bias[4], c[5].y + bias[5], c[6].y + bias[6], c[7].y + bias[7]};
        *(float4*)&C[r0] = lo0;
        *(float4*)&C[r0 + 4] = hi0;
        *(float4*)&C[r0 + N3] = lo1;
        *(float4*)&C[r0 + N3 + 4] = hi1;
    }
}

// ---------------- zero rings + barrier counters -----------------------------
__global__ void zero_misc() {
    int i = blockIdx.x * blockDim.x + threadIdx.x;
    int stride = gridDim.x * blockDim.x;
    for (int k = i; k < 8 * 32 * 1024; k += stride) g_hr[k] = 0.f;
    for (int k = i; k < 6 * 3072 * 32; k += stride) g_xr[k] = 0.f;
    if (i < 256) g_sub[i] = 0u;
    if (i == 0) { g_root = 0u; g_gen = 0u; }
}

// ============================================================================
// Wavefront tasks, 512 threads/CTA (16 warps -> 4/SMSP for latency cover;
// round-10 profile showed issue=29% at 2 warps/SMSP). Per global step s:
//   recur layer l : t = s - 2l       (h ring read s&1, write (s&1)^1;
//                                     xg ring read (s&1)^1 for l>=1)
//   xproj layer l : t = s - (2l-1)   (h ring (l-1) read s&1; xg write s&1)
// Weights streamed from L2 via 4-stage cp.async chunks of 32 k.
// Loops kept rolled (#pragma unroll 1) — full unroll exploded the cubin (R8).
// FINAL layer writes BOTH the h ring and dout (R9 bug).
// ============================================================================

// ---------------- recurrence task -------------------------------------------
template<int K, int UPW, int CUS, int LAYER, bool FINAL>
__device__ void run_recur(int cl, const float* __restrict__ whh,
                          const float* __restrict__ bhh,
                          const float* __restrict__ xg0, float* __restrict__ dout,
                          int tid, int cta, float* smem)
{
    constexpr int H = K;
    constexpr int CUP = UPW * 16;             // padded units per CTA (16 warps)
    constexpr int RS = 3 * CUP;               // staged W rows per chunk
    constexpr int NCH = K / 32;               // chunks per step
    constexpr int WG = RS * 8;                // W granules per chunk
    constexpr int TG = WG + 256;              // + h granules
    constexpr int GI = (TG + NTHR - 1) / NTHR;

    float* wb = smem;                          // [4][RS][32]
    float* hb = smem + 4 * RS * 32;            // [4][8][128]

    int warp = tid >> 5, lane = tid & 31;
    int ub = cl * CUS;
    int w0 = warp * UPW;

    bool uact[UPW]; int uidx[UPW]; float bhn[UPW]; float hreg[UPW];
#pragma unroll
    for (int uu = 0; uu < UPW; ++uu) {
        int ul = w0 + uu;
        int u = ub + ul;
        bool act = (ul < CUS) && (u < H);
        uact[uu] = act;
        uidx[uu] = act ? u : (H - 1);
        bhn[uu] = bhh[2 * H + uidx[uu]];
        hreg[uu] = 0.f;
    }

#pragma unroll 1
    for (int s = 0; s < NSTEPS; ++s) {
        int t = s - 2 * LAYER;
        bool active = (t >= 0) && (t < TT);
        if (active) {
            const float* hr_r = g_hr + (size_t)(LAYER * 2 + (s & 1)) * (32 * 1024);

            // prefetch xg for this step (consumed at epilogue)
            float xrv[UPW], xzv[UPW], xnv[UPW];
            if (LAYER == 0) {
                const float* xp = xg0 + ((size_t)lane * TT + t) * 1536;
#pragma unroll
                for (int uu = 0; uu < UPW; ++uu) {
                    int u = uidx[uu];
                    xrv[uu] = __ldcs(xp + u);
                    xzv[uu] = __ldcs(xp + 512 + u);
                    xnv[uu] = __ldcs(xp + 1024 + u);
                }
            } else {
                const float* xp = g_xr + (size_t)((LAYER - 1) * 2 + ((s & 1) ^ 1)) * (3072 * 32);
#pragma unroll
                for (int uu = 0; uu < UPW; ++uu) {
                    int u = uidx[uu];
                    xrv[uu] = __ldcg(xp + (size_t)u * 32 + lane);
                    xzv[uu] = __ldcg(xp + (size_t)(H + u) * 32 + lane);
                    xnv[uu] = __ldcg(xp + (size_t)(2 * H + u) * 32 + lane);
                }
            }

            auto stage = [&](int c) {
                int st = c & 3;
                int k0 = c * 32;
#pragma unroll
                for (int i = 0; i < GI; ++i) {
                    int idx = tid + i * NTHR;
                    if (idx < WG) {
                        int r = idx >> 3, g8 = idx & 7;
                        int gate = r / CUP, ul = r % CUP;
                        int u = ub + ul; if (u >= H) u = H - 1;
                        cpa16(&wb[(st * RS + r) * 32 + g8 * 4],
                              whh + (size_t)(gate * H + u) * K + k0 + g8 * 4);
                    } else if (idx < TG) {
                        int j = idx - WG;
                        int k4 = j >> 5, b = j & 31;
                        cpa16(&hb[(st * 8 + k4) * 128 + b * 4],
                              hr_r + (size_t)((k0 >> 2) + k4) * 128 + b * 4);
                    }
                }
                asm volatile("cp.async.commit_group;" ::: "memory");
            };
            stage(0); stage(1); stage(2);

            unsigned long long acc[3][UPW];
#pragma unroll
            for (int g = 0; g < 3; ++g)
#pragma unroll
                for (int uu = 0; uu < UPW; ++uu) acc[g][uu] = 0ull;

#pragma unroll 1
            for (int c = 0; c < NCH; ++c) {
                asm volatile("cp.async.wait_group 2;" ::: "memory");
                __syncthreads();           // chunk c landed everywhere; chunk c-1 consumed
                if (c + 3 < NCH) stage(c + 3);
                else asm volatile("cp.async.commit_group;" ::: "memory");
                int st = c & 3;
                const float* wcs = &wb[st * RS * 32];
                const float* hcs = &hb[st * 8 * 128];
#pragma unroll
                for (int k4 = 0; k4 < 8; ++k4) {
                    HU hv; hv.f = *(const float4*)&hcs[k4 * 128 + lane * 4];
#pragma unroll
                    for (int g = 0; g < 3; ++g)
#pragma unroll
                        for (int uu = 0; uu < UPW; ++uu) {
                            int r = g * CUP + w0 + uu;
                            ulonglong2 wv = *(const ulonglong2*)&wcs[r * 32 + k4 * 4];
                            fma2(acc[g][uu], hv.u.x, wv.x);
                            fma2(acc[g][uu], hv.u.y, wv.y);
                        }
                }
            }

            float* hr_w = g_hr + (size_t)(LAYER * 2 + ((s & 1) ^ 1)) * (32 * 1024);
#pragma unroll
            for (int uu = 0; uu < UPW; ++uu) {
                if (!uact[uu]) continue;
                int u = uidx[uu];
                float2 fr = up2(acc[0][uu]); float sr = fr.x + fr.y;
                float2 fz = up2(acc[1][uu]); float sz = fz.x + fz.y;
                float2 fn = up2(acc[2][uu]); float sn = fn.x + fn.y;
                float r_ = 1.f / (1.f + __expf(-(xrv[uu] + sr)));   // b_hh_r pre-folded into xg
                float z_ = 1.f / (1.f + __expf(-(xzv[uu] + sz)));   // b_hh_z pre-folded into xg
                float n_ = tanhf(xnv[uu] + r_ * (sn + bhn[uu]));
                float hnew = (1.f - z_) * n_ + z_ * hreg[uu];
                hreg[uu] = hnew;
                hr_w[(u >> 2) * 128 + lane * 4 + (u & 3)] = hnew;   // ALWAYS: own next step needs it
                if (FINAL)
                    __stcs(&dout[(size_t)lane * 1024 * TT + (size_t)u * TT + t], hnew);
            }
        }
        grid_barrier(tid, cta, (unsigned)(s + 1));
    }
}

// ---------------- input-projection task (layers 1..3) ------------------------
template<int K, int HOUT, int RPW, int RPC, int LAYER>
__device__ void run_xproj(int cl, const float* __restrict__ wih,
                          const float* __restrict__ bih, const float* __restrict__ bhh,
                          int tid, int cta, float* smem)
{
    constexpr int N3 = 3 * HOUT;
    constexpr int RSP = RPW * 16;
    constexpr int NCH = K / 32;
    constexpr int WG = RSP * 8;
    constexpr int TG = WG + 256;
    constexpr int GI = (TG + NTHR - 1) / NTHR;

    float* wb = smem;                          // [4][RSP][32]
    float* hb = smem + 4 * RSP * 32;           // [4][8][128]

    int warp = tid >> 5, lane = tid & 31;
    int rb = cl * RPC;
    int r0w = warp * RPW;

    bool ract[RPW]; int ridx[RPW]; float biasr[RPW];
#pragma unroll
    for (int rr = 0; rr < RPW; ++rr) {
        int rl = r0w + rr;
        int row = rb + rl;
        bool act = (rl < RPC) && (row < N3);
        ract[rr] = act;
        ridx[rr] = act ? row : (N3 - 1);
        biasr[rr] = bih[ridx[rr]] + (ridx[rr] < 2 * HOUT ? bhh[ridx[rr]] : 0.f);
    }

#pragma unroll 1
    for (int s = 0; s < NSTEPS; ++s) {
        int t = s - (2 * LAYER - 1);
        bool active = (t >= 0) && (t < TT);
        if (active) {
            const float* hr_r = g_hr + (size_t)((LAYER - 1) * 2 + (s & 1)) * (32 * 1024);
            float* xw = g_xr + (size_t)((LAYER - 1) * 2 + (s & 1)) * (3072 * 32);

            auto stage = [&](int c) {
                int st = c & 3;
                int k0 = c * 32;
#pragma unroll
                for (int i = 0; i < GI; ++i) {
                    int idx = tid + i * NTHR;
                    if (idx < WG) {
                        int r = idx >> 3, g8 = idx & 7;
                        int row = rb + r; if (row >= N3) row = N3 - 1;
                        cpa16(&wb[(st * RSP + r) * 32 + g8 * 4],
                              wih + (size_t)row * K + k0 + g8 * 4);
                    } else if (idx < TG) {
                        int j = idx - WG;
                        int k4 = j >> 5, b = j & 31;
                        cpa16(&hb[(st * 8 + k4) * 128 + b * 4],
                              hr_r + (size_t)((k0 >> 2) + k4) * 128 + b * 4);
                    }
                }
                asm volatile("cp.async.commit_group;" ::: "memory");
            };
            stage(0); stage(1); stage(2);

            unsigned long long acc[RPW];
#pragma unroll
            for (int rr = 0; rr < RPW; ++rr) acc[rr] = 0ull;

#pragma unroll 1
            for (int c = 0; c < NCH; ++c) {
                asm volatile("cp.async.wait_group 2;" ::: "memory");
                __syncthreads();
                if (c + 3 < NCH) stage(c + 3);
                else asm volatile("cp.async.commit_group;" ::: "memory");
                int st = c & 3;
                const float* wcs = &wb[st * RSP * 32];
                const float* hcs = &hb[st * 8 * 128];
#pragma unroll
                for (int k4 = 0; k4 < 8; ++k4) {
                    HU hv; hv.f = *(const float4*)&hcs[k4 * 128 + lane * 4];
#pragma unroll
                    for (int rr = 0; rr < RPW; ++rr) {
                        ulonglong2 wv = *(const ulonglong2*)&wcs[(r0w + rr) * 32 + k4 * 4];
                        fma2(acc[rr], hv.u.x, wv.x);
                        fma2(acc[rr], hv.u.y, wv.y);
                    }
                }
            }

#pragma unroll
            for (int rr = 0; rr < RPW; ++rr) {
                if (!ract[rr]) continue;
                float2 f = up2(acc[rr]);
                xw[(size_t)ridx[rr] * 32 + lane] = f.x + f.y + biasr[rr];
            }
        }
        grid_barrier(tid, cta, (unsigned)(s + 1));
    }
}

// ---------------- mega kernel: all tasks, one launch -------------------------
__global__ __launch_bounds__(NTHR, 1) void mega(
    float* __restrict__ dout,
    const float* whh0, const float* bhh0,
    const float* wih1, const float* bih1, const float* whh1, const float* bhh1,
    const float* wih2, const float* bih2, const float* whh2, const float* bhh2,
    const float* wih3, const float* bih3, const float* whh3, const float* bhh3)
{
    extern __shared__ __align__(16) float smem[];
    int tid = threadIdx.x, cta = blockIdx.x;
    if      (cta <   9) run_recur< 512, 4, 57, 0, false>(cta,       whh0, bhh0, g_xg, nullptr, tid, cta, smem);
    else if (cta <  18) run_xproj< 512,  512, 11, 171, 1>(cta -   9, wih1, bih1, bhh1, tid, cta, smem);
    else if (cta <  27) run_recur< 512, 4, 57, 1, false>(cta -  18, whh1, bhh1, nullptr, nullptr, tid, cta, smem);
    else if (cta <  44) run_xproj< 512, 1024, 12, 181, 2>(cta -  27, wih2, bih2, bhh2, tid, cta, smem);
    else if (cta <  79) run_recur<1024, 2, 30, 2, false>(cta -  44, whh2, bhh2, nullptr, nullptr, tid, cta, smem);
    else if (cta < 113) run_xproj<1024, 1024,  6,  91, 3>(cta -  79, wih3, bih3, bhh3, tid, cta, smem);
    else                run_recur<1024, 2, 30, 3, true >(cta - 113, whh3, bhh3, nullptr, dout, tid, cta, smem);
}

extern "C" void kernel_launch(void* const* d_in, const int* in_sizes, int n_in,
                              void* d_out, int out_size) {
    const float* x = (const float*)d_in[0];
    const float* wih[4]; const float* whh[4]; const float* bih[4]; const float* bhh[4];
    for (int l = 0; l < 4; ++l) {
        wih[l] = (const float*)d_in[1 + 4 * l];
        whh[l] = (const float*)d_in[2 + 4 * l];
        bih[l] = (const float*)d_in[3 + 4 * l];
        bhh[l] = (const float*)d_in[4 + 4 * l];
    }
    float *xg, *wT;
    cudaGetSymbolAddress((void**)&xg, g_xg);
    cudaGetSymbolAddress((void**)&wT, g_wT);
    float* dout = (float*)d_out;

    const int SMEMG = 3 * 16 * 128 * 4 * 2;                     // 49152 B
    const int SMEMM = (4 * 192 * 32 + 4 * 8 * 128) * 4;         // 114688 B (max task: RS/RSP=192)
    cudaFuncSetAttribute(gemm_xg, cudaFuncAttributeMaxDynamicSharedMemorySize, SMEMG);
    cudaFuncSetAttribute(mega, cudaFuncAttributeMaxDynamicSharedMemorySize, SMEMM);

    // L0 bulk input projection: x is [B][256][T] (t contiguous)
    transpose_w<<<dim3(256 / 32, 1536 / 32), dim3(32, 8)>>>(wih[0], wT, 256, 1536);
    gemm_xg<<<dim3(1536 / 128, (BB * TT) / 128), 256, SMEMG>>>(
        x, wT, bih[0], bhh[0], xg, 256, 1536, 512, (long)256 * 2048);
    zero_misc<<<512, 256>>>();
    mega<<<GRID, NTHR, SMEMM>>>(
        dout,
        whh[0], bhh[0],
        wih[1], bih[1], whh[1], bhh[1],
        wih[2], bih[2], whh[2], bhh[2],
        wih[3], bih[3], whh[3], bhh[3]);
}

// round 12
// speedup vs baseline: 1.3059x; 1.3059x over previous
#include <cuda_runtime.h>
#include <cstdint>

constexpr int BB = 32;       // batch
constexpr int TT = 2048;     // time steps
constexpr int NSTEPS = TT + 6;
constexpr int GRID = 148;    // 4 * 37 exactly
constexpr int NTHR = 256;    // 8 warps

// ---------------- scratch (static device globals) ---------------------------
__device__ float g_xg[(size_t)BB * TT * 1536];   // L0 input projections [b*TT+t][1536]
__device__ float g_wT[256 * 1536];               // L0 w_ih transposed [K][3H]
__device__ float g_hr[8 * 32 * 1024];            // h rings [layer][par], plain [k][b]
__device__ float g_xr[6 * 3072 * 32];            // xg rings [layer-1][par][row][b]
__device__ unsigned g_sub[4 * 64];               // tree barrier sub-counters (256B-strided)
__device__ unsigned g_root;
__device__ unsigned g_gen;

// ---------------- packed f32x2 helpers --------------------------------------
__device__ __forceinline__ void fma2(unsigned long long& a, unsigned long long x, unsigned long long y) {
    asm("fma.rn.f32x2 %0, %1, %2, %0;" : "+l"(a) : "l"(x), "l"(y));
}
__device__ __forceinline__ unsigned long long pk2(float x, float y) {
    unsigned long long r; asm("mov.b64 %0, {%1,%2};" : "=l"(r) : "f"(x), "f"(y)); return r;
}
__device__ __forceinline__ float2 up2(unsigned long long v) {
    float2 f; asm("mov.b64 {%0,%1}, %2;" : "=f"(f.x), "=f"(f.y) : "l"(v)); return f;
}
__device__ __forceinline__ unsigned long long add2(unsigned long long a, unsigned long long b) {
    unsigned long long r; asm("add.rn.f32x2 %0, %1, %2;" : "=l"(r) : "l"(a), "l"(b)); return r;
}
union HU { float4 f; ulonglong2 u; };

__device__ __forceinline__ void cpa16(void* dst, const void* src) {
    uint32_t d = (uint32_t)__cvta_generic_to_shared(dst);
    asm volatile("cp.async.cg.shared.global [%0], [%1], 16;" :: "r"(d), "l"(src));
}
__device__ __forceinline__ void st_rel(unsigned* p, unsigned v) {
    asm volatile("st.release.gpu.global.u32 [%0], %1;" :: "l"(p), "r"(v) : "memory");
}
__device__ __forceinline__ unsigned ld_acq(const unsigned* p) {
    unsigned v;
    asm volatile("ld.acquire.gpu.global.u32 %0, [%1];" : "=r"(v) : "l"(p) : "memory");
    return v;
}
__device__ __forceinline__ unsigned atom_add_ar(unsigned* p, unsigned v) {
    unsigned old;
    asm volatile("atom.acq_rel.gpu.global.add.u32 %0, [%1], %2;"
                 : "=r"(old) : "l"(p), "r"(v) : "memory");
    return old;
}

// ---------------- tree grid barrier -----------------------------------------
__device__ __forceinline__ void grid_barrier(int tid, int cta, unsigned tstep) {
    __syncthreads();
    if (tid == 0) {
        int sub = cta & 3;
        unsigned old = atom_add_ar(&g_sub[sub * 64], 1u);
        bool rootlast = false;
        if (old + 1u == 37u * tstep) {
            unsigned ro = atom_add_ar(&g_root, 1u);
            if (ro + 1u == 4u * tstep) { st_rel(&g_gen, tstep); rootlast = true; }
        }
        if (!rootlast)
            while ((int)(ld_acq(&g_gen) - tstep) < 0) { }
    }
    __syncthreads();
}

// ---------------- one-shot weight transpose: Wt[k][n] = W[n][k] -------------
__global__ void transpose_w(const float* __restrict__ W, float* __restrict__ Wt,
                            int K, int N3)
{
    __shared__ float tile[32][33];
    int kb = blockIdx.x * 32, nb = blockIdx.y * 32;
    for (int r = threadIdx.y; r < 32; r += 8)
        tile[r][threadIdx.x] = W[(size_t)(nb + r) * K + kb + threadIdx.x];
    __syncthreads();
    for (int r = threadIdx.y; r < 32; r += 8)
        Wt[(size_t)(kb + r) * N3 + nb + threadIdx.x] = tile[threadIdx.x][r];
}

// ---------------- bulk L0 input-projection GEMM (proven) --------------------
__global__ __launch_bounds__(256, 2) void gemm_xg(
    const float* __restrict__ A, const float* __restrict__ Wt,
    const float* __restrict__ bih, const float* __restrict__ bhh,
    float* __restrict__ C, int K, int N3, int H, long sb)
{
    extern __shared__ __align__(16) float dsm[];
    float* As = dsm;                    // [3][16][128]
    float* Bs = dsm + 3 * 16 * 128;     // [3][16][128]

    int tid = threadIdx.x;
    int n0 = blockIdx.x * 128;
    int m0 = blockIdx.y * 128;
    int bidx = m0 / TT;
    int t0 = m0 % TT;
    const float* Ab = A + (size_t)bidx * sb + t0;
    int tx = tid & 15, ty = tid >> 4;

    unsigned long long acc[4][8];
#pragma unroll
    for (int p = 0; p < 4; ++p)
#pragma unroll
        for (int j = 0; j < 8; ++j) acc[p][j] = 0ull;

    auto issue = [&](int s, int k0) {
#pragma unroll
        for (int i = 0; i < 2; ++i) {
            int lin = tid + i * 256;
            int k = lin >> 5, q4 = (lin & 31) * 4;
            cpa16(&As[(s * 16 + k) * 128 + q4], Ab + q4 + (size_t)(k0 + k) * TT);
            cpa16(&Bs[(s * 16 + k) * 128 + q4], &Wt[(size_t)(k0 + k) * N3 + n0 + q4]);
        }
    };

    issue(0, 0);  asm volatile("cp.async.commit_group;" ::: "memory");
    issue(1, 16); asm volatile("cp.async.commit_group;" ::: "memory");

    int s = 0;
#pragma unroll 1
    for (int k0 = 0; k0 < K; k0 += 16) {
        asm volatile("cp.async.wait_group 1;" ::: "memory");
        __syncthreads();
        if (k0 + 32 < K) issue((s + 2) % 3, k0 + 32);
        asm volatile("cp.async.commit_group;" ::: "memory");

        const float* Ak = &As[s * 16 * 128];
        const float* Bk = &Bs[s * 16 * 128];
#pragma unroll
        for (int k = 0; k < 16; ++k) {
            const ulonglong2* ap = (const ulonglong2*)&Ak[k * 128 + ty * 8];
            ulonglong2 A0 = ap[0], A1 = ap[1];
            unsigned long long am[4] = {A0.x, A0.y, A1.x, A1.y};
            float4 b0 = *(const float4*)&Bk[k * 128 + tx * 8];
            float4 b1 = *(const float4*)&Bk[k * 128 + tx * 8 + 4];
            unsigned long long bd[8] = {pk2(b0.x, b0.x), pk2(b0.y, b0.y),
                                        pk2(b0.z, b0.z), pk2(b0.w, b0.w),
                                        pk2(b1.x, b1.x), pk2(b1.y, b1.y),
                                        pk2(b1.z, b1.z), pk2(b1.w, b1.w)};
#pragma unroll
            for (int p = 0; p < 4; ++p)
#pragma unroll
                for (int j = 0; j < 8; ++j) fma2(acc[p][j], am[p], bd[j]);
        }
        s = (s == 2) ? 0 : s + 1;
    }

    float bias[8];
#pragma unroll
    for (int j = 0; j < 8; ++j) {
        int n = n0 + tx * 8 + j;
        bias[j] = bih[n] + (n < 2 * H ? bhh[n] : 0.f);
    }
#pragma unroll
    for (int p = 0; p < 4; ++p) {
        float2 c[8];
#pragma unroll
        for (int j = 0; j < 8; ++j) c[j] = up2(acc[p][j]);
        size_t r0 = (size_t)(m0 + ty * 8 + 2 * p) * N3 + n0 + tx * 8;
        float4 lo0 = {c[0].x + bias[0], c[1].x + bias[1], c[2].x + bias[2], c[3].x + bias[3]};
        float4 hi0 = {c[4].x + bias[4], c[5].x + bias[5], c[6].x + bias[6], c[7].x + bias[7]};
        float4 lo1 = {c[0].y + bias[0], c[1].y + bias[1], c[2].y + bias[2], c[3].y + bias[3]};
        float4 hi1 = {c[4].y + bias[4], c[5].y + bias[5], c[6].y + bias[6], c[7].y + bias[7]};
        *(float4*)&C[r0] = lo0;
        *(float4*)&C[r0 + 4] = hi0;
        *(float4*)&C[r0 + N3] = lo1;
        *(float4*)&C[r0 + N3 + 4] = hi1;
    }
}

// ---------------- zero rings + barrier counters -----------------------------
__global__ void zero_misc() {
    int i = blockIdx.x * blockDim.x + threadIdx.x;
    int stride = gridDim.x * blockDim.x;
    for (int k = i; k < 8 * 32 * 1024; k += stride) g_hr[k] = 0.f;
    for (int k = i; k < 6 * 3072 * 32; k += stride) g_xr[k] = 0.f;
    if (i < 256) g_sub[i] = 0u;
    if (i == 0) { g_root = 0u; g_gen = 0u; }
}

// ============================================================================
// Wavefront tasks — NEW lane mapping (kg = lane>>3, bg = lane&7):
// h packed f32x2 over batch pairs (ring layout plain [k][b]); weights loaded
// as float4 with only 4 distinct addresses/warp (64B per crossbar wavefront
// vs 16B broadcast before). k-partials reduced via 2 shfl-xor levels (8,16).
// Epilogues: compile-time-unrolled rows/units with (idx&3)==kg predicate, so
// no dynamic register indexing. Everything else is round-10 verbatim.
// ============================================================================

// ---------------- recurrence task -------------------------------------------
template<int K, int UPW, int CUS, int LAYER, bool FINAL>
__device__ void run_recur(int cl, const float* __restrict__ whh,
                          const float* __restrict__ bhh,
                          const float* __restrict__ xg0, float* __restrict__ dout,
                          int tid, int cta, float* smem)
{
    constexpr int H = K;
    constexpr int CUP = UPW * 8;              // padded units per CTA
    constexpr int RS = 3 * CUP;               // staged W rows per chunk
    constexpr int NCH = K / 32;               // chunks per step
    constexpr int WG = RS * 8;                // W granules per chunk
    constexpr int TG = WG + 256;              // + h granules
    constexpr int GI = (TG + NTHR - 1) / NTHR;
    constexpr int NU4 = (UPW + 3) / 4;        // units per kg lane

    float* wb = smem;                          // [4][RS][32]
    float* hb = smem + 4 * RS * 32;            // [4][32 k][32 b]

    int warp = tid >> 5, lane = tid & 31;
    int kg = lane >> 3, bg = lane & 7;
    int ub = cl * CUS;
    int w0 = warp * UPW;

    bool uact[UPW]; int uidx[UPW]; float bhn[UPW];
#pragma unroll
    for (int uu = 0; uu < UPW; ++uu) {
        int ul = w0 + uu;
        int u = ub + ul;
        bool act = (ul < CUS) && (u < H);
        uact[uu] = act;
        uidx[uu] = act ? u : (H - 1);
        bhn[uu] = bhh[2 * H + uidx[uu]];
    }
    float hreg[NU4][4];
#pragma unroll
    for (int i = 0; i < NU4; ++i)
#pragma unroll
        for (int e = 0; e < 4; ++e) hreg[i][e] = 0.f;

#pragma unroll 1
    for (int s = 0; s < NSTEPS; ++s) {
        int t = s - 2 * LAYER;
        bool active = (t >= 0) && (t < TT);
        if (active) {
            const float* hr_r = g_hr + (size_t)(LAYER * 2 + (s & 1)) * (32 * 1024);

            auto stage = [&](int c) {
                int st = c & 3;
                int k0 = c * 32;
#pragma unroll
                for (int i = 0; i < GI; ++i) {
                    int idx = tid + i * NTHR;
                    if (idx < WG) {
                        int r = idx >> 3, g8 = idx & 7;
                        int gate = r / CUP, ul = r % CUP;
                        int u = ub + ul; if (u >= H) u = H - 1;
                        cpa16(&wb[(st * RS + r) * 32 + g8 * 4],
                              whh + (size_t)(gate * H + u) * K + k0 + g8 * 4);
                    } else if (idx < TG) {
                        int j = idx - WG;
                        int kk = j >> 3, b4 = j & 7;
                        cpa16(&hb[(st * 32 + kk) * 32 + b4 * 4],
                              hr_r + (size_t)(k0 + kk) * 32 + b4 * 4);
                    }
                }
                asm volatile("cp.async.commit_group;" ::: "memory");
            };
            stage(0); stage(1); stage(2);

            // prefetch xg for this lane's units (compile-time uu, kg-predicated)
            float xrv[NU4][4], xzv[NU4][4], xnv[NU4][4];
#pragma unroll
            for (int uu = 0; uu < UPW; ++uu) {
                if ((uu & 3) != kg) continue;
                const int h8 = uu >> 2;
                int u = uidx[uu];
                if (LAYER == 0) {
#pragma unroll
                    for (int e = 0; e < 4; ++e) {
                        const float* xp = xg0 + ((size_t)(bg * 4 + e) * TT + t) * 1536;
                        xrv[h8][e] = __ldcs(xp + u);
                        xzv[h8][e] = __ldcs(xp + 512 + u);
                        xnv[h8][e] = __ldcs(xp + 1024 + u);
                    }
                } else {
                    const float* xp = g_xr + (size_t)((LAYER - 1) * 2 + ((s & 1) ^ 1)) * (3072 * 32);
                    float4 a = __ldcg((const float4*)&xp[(size_t)u * 32 + bg * 4]);
                    float4 bz = __ldcg((const float4*)&xp[(size_t)(H + u) * 32 + bg * 4]);
                    float4 cn = __ldcg((const float4*)&xp[(size_t)(2 * H + u) * 32 + bg * 4]);
                    xrv[h8][0] = a.x;  xrv[h8][1] = a.y;  xrv[h8][2] = a.z;  xrv[h8][3] = a.w;
                    xzv[h8][0] = bz.x; xzv[h8][1] = bz.y; xzv[h8][2] = bz.z; xzv[h8][3] = bz.w;
                    xnv[h8][0] = cn.x; xnv[h8][1] = cn.y; xnv[h8][2] = cn.z; xnv[h8][3] = cn.w;
                }
            }

            unsigned long long acc[3][UPW][2];
#pragma unroll
            for (int g = 0; g < 3; ++g)
#pragma unroll
                for (int uu = 0; uu < UPW; ++uu) { acc[g][uu][0] = 0ull; acc[g][uu][1] = 0ull; }

#pragma unroll 1
            for (int c = 0; c < NCH; ++c) {
                asm volatile("cp.async.wait_group 2;" ::: "memory");
                __syncthreads();
                if (c + 3 < NCH) stage(c + 3);
                else asm volatile("cp.async.commit_group;" ::: "memory");
                int st = c & 3;
                const float* wcs = &wb[st * RS * 32];
                const float* hcs = &hb[st * 32 * 32];
#pragma unroll
                for (int hf = 0; hf < 2; ++hf) {
                    HU hv[4];
#pragma unroll
                    for (int j = 0; j < 4; ++j)
                        hv[j].f = *(const float4*)&hcs[(kg * 8 + hf * 4 + j) * 32 + bg * 4];
#pragma unroll
                    for (int g = 0; g < 3; ++g)
#pragma unroll
                        for (int uu = 0; uu < UPW; ++uu) {
                            int r = g * CUP + w0 + uu;
                            float4 wv = *(const float4*)&wcs[r * 32 + kg * 8 + hf * 4];
                            unsigned long long w2;
                            w2 = pk2(wv.x, wv.x);
                            fma2(acc[g][uu][0], hv[0].u.x, w2); fma2(acc[g][uu][1], hv[0].u.y, w2);
                            w2 = pk2(wv.y, wv.y);
                            fma2(acc[g][uu][0], hv[1].u.x, w2); fma2(acc[g][uu][1], hv[1].u.y, w2);
                            w2 = pk2(wv.z, wv.z);
                            fma2(acc[g][uu][0], hv[2].u.x, w2); fma2(acc[g][uu][1], hv[2].u.y, w2);
                            w2 = pk2(wv.w, wv.w);
                            fma2(acc[g][uu][0], hv[3].u.x, w2); fma2(acc[g][uu][1], hv[3].u.y, w2);
                        }
                }
            }

            // reduce partial sums over kg (lane bits 3,4)
#pragma unroll
            for (int g = 0; g < 3; ++g)
#pragma unroll
                for (int uu = 0; uu < UPW; ++uu)
#pragma unroll
                    for (int p = 0; p < 2; ++p) {
                        unsigned long long v = acc[g][uu][p];
                        v = add2(v, __shfl_xor_sync(0xffffffffu, v, 8));
                        v = add2(v, __shfl_xor_sync(0xffffffffu, v, 16));
                        acc[g][uu][p] = v;
                    }

            float* hr_w = g_hr + (size_t)(LAYER * 2 + ((s & 1) ^ 1)) * (32 * 1024);
#pragma unroll
            for (int uu = 0; uu < UPW; ++uu) {
                if ((uu & 3) != kg) continue;
                if (!uact[uu]) continue;
                const int h8 = uu >> 2;
                int u = uidx[uu];
                float2 r0 = up2(acc[0][uu][0]), r1 = up2(acc[0][uu][1]);
                float2 z0 = up2(acc[1][uu][0]), z1 = up2(acc[1][uu][1]);
                float2 n0 = up2(acc[2][uu][0]), n1 = up2(acc[2][uu][1]);
                float srv[4] = {r0.x, r0.y, r1.x, r1.y};
                float szv[4] = {z0.x, z0.y, z1.x, z1.y};
                float snv[4] = {n0.x, n0.y, n1.x, n1.y};
                float4 o;
                float* op = (float*)&o;
#pragma unroll
                for (int e = 0; e < 4; ++e) {
                    float r_ = 1.f / (1.f + __expf(-(xrv[h8][e] + srv[e])));
                    float z_ = 1.f / (1.f + __expf(-(xzv[h8][e] + szv[e])));
                    float n_ = tanhf(xnv[h8][e] + r_ * (snv[e] + bhn[uu]));
                    float hnew = (1.f - z_) * n_ + z_ * hreg[h8][e];
                    hreg[h8][e] = hnew;
                    op[e] = hnew;
                    if (FINAL)
                        __stcs(&dout[(size_t)(bg * 4 + e) * 1024 * TT + (size_t)u * TT + t], hnew);
                }
                *(float4*)&hr_w[u * 32 + bg * 4] = o;
            }
        }
        grid_barrier(tid, cta, (unsigned)(s + 1));
    }
}

// ---------------- input-projection task (layers 1..3) ------------------------
template<int K, int HOUT, int RPW, int RPC, int LAYER>
__device__ void run_xproj(int cl, const float* __restrict__ wih,
                          const float* __restrict__ bih, const float* __restrict__ bhh,
                          int tid, int cta, float* smem)
{
    constexpr int N3 = 3 * HOUT;
    constexpr int RSP = RPW * 8;
    constexpr int NCH = K / 32;
    constexpr int WG = RSP * 8;
    constexpr int TG = WG + 256;
    constexpr int GI = (TG + NTHR - 1) / NTHR;

    float* wb = smem;                          // [4][RSP][32]
    float* hb = smem + 4 * RSP * 32;           // [4][32][32]

    int warp = tid >> 5, lane = tid & 31;
    int kg = lane >> 3, bg = lane & 7;
    int rb = cl * RPC;
    int r0w = warp * RPW;

    bool ract[RPW]; int ridx[RPW]; float biasr[RPW];
#pragma unroll
    for (int rr = 0; rr < RPW; ++rr) {
        int rl = r0w + rr;
        int row = rb + rl;
        bool act = (rl < RPC) && (row < N3);
        ract[rr] = act;
        ridx[rr] = act ? row : (N3 - 1);
        biasr[rr] = bih[ridx[rr]] + (ridx[rr] < 2 * HOUT ? bhh[ridx[rr]] : 0.f);
    }

#pragma unroll 1
    for (int s = 0; s < NSTEPS; ++s) {
        int t = s - (2 * LAYER - 1);
        bool active = (t >= 0) && (t < TT);
        if (active) {
            const float* hr_r = g_hr + (size_t)((LAYER - 1) * 2 + (s & 1)) * (32 * 1024);
            float* xw = g_xr + (size_t)((LAYER - 1) * 2 + (s & 1)) * (3072 * 32);

            auto stage = [&](int c) {
                int st = c & 3;
                int k0 = c * 32;
#pragma unroll
                for (int i = 0; i < GI; ++i) {
                    int idx = tid + i * NTHR;
                    if (idx < WG) {
                        int r = idx >> 3, g8 = idx & 7;
                        int row = rb + r; if (row >= N3) row = N3 - 1;
                        cpa16(&wb[(st * RSP + r) * 32 + g8 * 4],
                              wih + (size_t)row * K + k0 + g8 * 4);
                    } else if (idx < TG) {
                        int j = idx - WG;
                        int kk = j >> 3, b4 = j & 7;
                        cpa16(&hb[(st * 32 + kk) * 32 + b4 * 4],
                              hr_r + (size_t)(k0 + kk) * 32 + b4 * 4);
                    }
                }
                asm volatile("cp.async.commit_group;" ::: "memory");
            };
            stage(0); stage(1); stage(2);

            unsigned long long acc[RPW][2];
#pragma unroll
            for (int rr = 0; rr < RPW; ++rr) { acc[rr][0] = 0ull; acc[rr][1] = 0ull; }

#pragma unroll 1
            for (int c = 0; c < NCH; ++c) {
                asm volatile("cp.async.wait_group 2;" ::: "memory");
                __syncthreads();
                if (c + 3 < NCH) stage(c + 3);
                else asm volatile("cp.async.commit_group;" ::: "memory");
                int st = c & 3;
                const float* wcs = &wb[st * RSP * 32];
                const float* hcs = &hb[st * 32 * 32];
#pragma unroll
                for (int hf = 0; hf < 2; ++hf) {
                    HU hv[4];
#pragma unroll
                    for (int j = 0; j < 4; ++j)
                        hv[j].f = *(const float4*)&hcs[(kg * 8 + hf * 4 + j) * 32 + bg * 4];
#pragma unroll
                    for (int rr = 0; rr < RPW; ++rr) {
                        float4 wv = *(const float4*)&wcs[(r0w + rr) * 32 + kg * 8 + hf * 4];
                        unsigned long long w2;
                        w2 = pk2(wv.x, wv.x);
                        fma2(acc[rr][0], hv[0].u.x, w2); fma2(acc[rr][1], hv[0].u.y, w2);
                        w2 = pk2(wv.y, wv.y);
                        fma2(acc[rr][0], hv[1].u.x, w2); fma2(acc[rr][1], hv[1].u.y, w2);
                        w2 = pk2(wv.z, wv.z);
                        fma2(acc[rr][0], hv[2].u.x, w2); fma2(acc[rr][1], hv[2].u.y, w2);
                        w2 = pk2(wv.w, wv.w);
                        fma2(acc[rr][0], hv[3].u.x, w2); fma2(acc[rr][1], hv[3].u.y, w2);
                    }
                }
            }

            // reduce over kg
#pragma unroll
            for (int rr = 0; rr < RPW; ++rr)
#pragma unroll
                for (int p = 0; p < 2; ++p) {
                    unsigned long long v = acc[rr][p];
                    v = add2(v, __shfl_xor_sync(0xffffffffu, v, 8));
                    v = add2(v, __shfl_xor_sync(0xffffffffu, v, 16));
                    acc[rr][p] = v;
                }

#pragma unroll
            for (int rr = 0; rr < RPW; ++rr) {
                if ((rr & 3) != kg) continue;
                if (!ract[rr]) continue;
                float2 a0 = up2(acc[rr][0]), a1 = up2(acc[rr][1]);
                float b = biasr[rr];
                float4 o = make_float4(a0.x + b, a0.y + b, a1.x + b, a1.y + b);
                *(float4*)&xw[(size_t)ridx[rr] * 32 + bg * 4] = o;
            }
        }
        grid_barrier(tid, cta, (unsigned)(s + 1));
    }
}

// ---------------- mega kernel: all tasks, one launch -------------------------
__global__ __launch_bounds__(NTHR, 1) void mega(
    float* __restrict__ dout,
    const float* whh0, const float* bhh0,
    const float* wih1, const float* bih1, const float* whh1, const float* bhh1,
    const float* wih2, const float* bih2, const float* whh2, const float* bhh2,
    const float* wih3, const float* bih3, const float* whh3, const float* bhh3)
{
    extern __shared__ __align__(16) float smem[];
    int tid = threadIdx.x, cta = blockIdx.x;
    if      (cta <   9) run_recur< 512, 8, 57, 0, false>(cta,       whh0, bhh0, g_xg, nullptr, tid, cta, smem);
    else if (cta <  18) run_xproj< 512,  512, 22, 171, 1>(cta -   9, wih1, bih1, bhh1, tid, cta, smem);
    else if (cta <  27) run_recur< 512, 8, 57, 1, false>(cta -  18, whh1, bhh1, nullptr, nullptr, tid, cta, smem);
    else if (cta <  44) run_xproj< 512, 1024, 23, 181, 2>(cta -  27, wih2, bih2, bhh2, tid, cta, smem);
    else if (cta <  79) run_recur<1024, 4, 30, 2, false>(cta -  44, whh2, bhh2, nullptr, nullptr, tid, cta, smem);
    else if (cta < 113) run_xproj<1024, 1024, 12,  91, 3>(cta -  79, wih3, bih3, bhh3, tid, cta, smem);
    else                run_recur<1024, 4, 30, 3, true >(cta - 113, whh3, bhh3, nullptr, dout, tid, cta, smem);
}

extern "C" void kernel_launch(void* const* d_in, const int* in_sizes, int n_in,
                              void* d_out, int out_size) {
    const float* x = (const float*)d_in[0];
    const float* wih[4]; const float* whh[4]; const float* bih[4]; const float* bhh[4];
    for (int l = 0; l < 4; ++l) {
        wih[l] = (const float*)d_in[1 + 4 * l];
        whh[l] = (const float*)d_in[2 + 4 * l];
        bih[l] = (const float*)d_in[3 + 4 * l];
        bhh[l] = (const float*)d_in[4 + 4 * l];
    }
    float *xg, *wT;
    cudaGetSymbolAddress((void**)&xg, g_xg);
    cudaGetSymbolAddress((void**)&wT, g_wT);
    float* dout = (float*)d_out;

    const int SMEMG = 3 * 16 * 128 * 4 * 2;                     // 49152 B
    const int SMEMM = (4 * 192 * 32 + 4 * 32 * 32) * 4;         // 114688 B (max: RS=192)
    cudaFuncSetAttribute(gemm_xg, cudaFuncAttributeMaxDynamicSharedMemorySize, SMEMG);
    cudaFuncSetAttribute(mega, cudaFuncAttributeMaxDynamicSharedMemorySize, SMEMM);

    // L0 bulk input projection: x is [B][256][T] (t contiguous)
    transpose_w<<<dim3(256 / 32, 1536 / 32), dim3(32, 8)>>>(wih[0], wT, 256, 1536);
    gemm_xg<<<dim3(1536 / 128, (BB * TT) / 128), 256, SMEMG>>>(
        x, wT, bih[0], bhh[0], xg, 256, 1536, 512, (long)256 * 2048);
    zero_misc<<<512, 256>>>();
    mega<<<GRID, NTHR, SMEMM>>>(
        dout,
        whh[0], bhh[0],
        wih[1], bih[1], whh[1], bhh[1],
        wih[2], bih[2], whh[2], bhh[2],
        wih[3], bih[3], whh[3], bhh[3]);
}